// round 2
// baseline (speedup 1.0000x reference)
#include <cuda_runtime.h>
#include <cstdint>

#define BATCH 8192
#define NNEI  32
#define DIN   512
#define DHID  512
#define DOUT  512

#define LDA 36     // words; 144B row stride (16B aligned)
#define LDB 136    // words; 544B row stride (16B aligned)
#define STAGE_WORDS (128 * LDA + 32 * LDB)   // 4608 + 4352 = 8960
#define SMEM_BYTES (2 * STAGE_WORDS * 4)     // 71680

// Scratch for pooled activations [BATCH, DHID]
__device__ float g_pooled[BATCH * DHID];

__device__ __forceinline__ uint32_t f2tf(float x) {
    uint32_t r;
    asm("cvt.rna.tf32.f32 %0, %1;" : "=r"(r) : "f"(x));
    return r;
}

__device__ __forceinline__ void cp_async16(float* smem_dst, const float* gsrc) {
    uint32_t s = (uint32_t)__cvta_generic_to_shared(smem_dst);
    asm volatile("cp.async.cg.shared.global [%0], [%1], 16;\n" :: "r"(s), "l"(gsrc));
}
#define CP_COMMIT() asm volatile("cp.async.commit_group;\n" ::: "memory")
#define CP_WAIT0()  asm volatile("cp.async.wait_group 0;\n" ::: "memory")

__device__ __forceinline__ void mma8(float* c,
                                     uint32_t a0, uint32_t a1, uint32_t a2, uint32_t a3,
                                     uint32_t b0, uint32_t b1) {
    asm volatile(
        "mma.sync.aligned.m16n8k8.row.col.f32.tf32.tf32.f32 "
        "{%0,%1,%2,%3},{%4,%5,%6,%7},{%8,%9},{%0,%1,%2,%3};\n"
        : "+f"(c[0]), "+f"(c[1]), "+f"(c[2]), "+f"(c[3])
        : "r"(a0), "r"(a1), "r"(a2), "r"(a3), "r"(b0), "r"(b1));
}

// Async-issue one K-chunk (32) of A[128x32] and W[32x128] into a smem stage (raw fp32).
__device__ __forceinline__ void issue_tiles(const float* __restrict__ A,
                                            const float* __restrict__ W,
                                            int rowBase, int kt, int nBase,
                                            float* As, float* Bs, int tid) {
#pragma unroll
    for (int j = 0; j < 4; j++) {
        int pos = tid + j * 256;          // 128 rows x 8 float4
        int r  = pos >> 3;
        int kq = pos & 7;
        cp_async16(As + r * LDA + kq * 4, A + (rowBase + r) * DIN + kt * 32 + kq * 4);
    }
#pragma unroll
    for (int j = 0; j < 4; j++) {
        int pos = tid + j * 256;          // 32 k-rows x 32 float4
        int kr = pos >> 5;
        int nq = pos & 31;
        cp_async16(Bs + kr * LDB + nq * 4, W + (kt * 32 + kr) * DHID + nBase + nq * 4);
    }
}

// One K-chunk of MMAs for this warp's 32x64 tile. cvt.rna applied on fragments.
__device__ __forceinline__ void compute_chunk(const float* As, const float* Bs,
                                              float c[2][8][4],
                                              int warpM, int warpN, int g, int tig) {
#pragma unroll
    for (int k8 = 0; k8 < 4; k8++) {
        int kk = k8 * 8;
        uint32_t a[2][4];
#pragma unroll
        for (int mt = 0; mt < 2; mt++) {
            int rb = warpM * 32 + mt * 16;
            a[mt][0] = f2tf(As[(rb + g) * LDA + kk + tig]);
            a[mt][1] = f2tf(As[(rb + g + 8) * LDA + kk + tig]);
            a[mt][2] = f2tf(As[(rb + g) * LDA + kk + tig + 4]);
            a[mt][3] = f2tf(As[(rb + g + 8) * LDA + kk + tig + 4]);
        }
        uint32_t b[8][2];
#pragma unroll
        for (int nt = 0; nt < 8; nt++) {
            int nb = warpN * 64 + nt * 8 + g;
            b[nt][0] = f2tf(Bs[(kk + tig) * LDB + nb]);
            b[nt][1] = f2tf(Bs[(kk + tig + 4) * LDB + nb]);
        }
#pragma unroll
        for (int mt = 0; mt < 2; mt++)
#pragma unroll
            for (int nt = 0; nt < 8; nt++)
                mma8(c[mt][nt], a[mt][0], a[mt][1], a[mt][2], a[mt][3], b[nt][0], b[nt][1]);
    }
}

// Kernel 1: h = neigh_vecs @ mlp_w; pooled = relu(max_over_32rows(h) + b)
__global__ void __launch_bounds__(256, 2)
k_mlp_maxpool(const float* __restrict__ neigh,
              const float* __restrict__ mlp_w,
              const float* __restrict__ mlp_b) {
    extern __shared__ float sm[];

    int tid  = threadIdx.x;
    int warp = tid >> 5, lane = tid & 31;
    int g = lane >> 2, tig = lane & 3;
    int warpM = warp & 3, warpN = warp >> 2;

    int rowBase = blockIdx.y * 128;
    int nBase   = blockIdx.x * 128;

    float c[2][8][4];
#pragma unroll
    for (int mt = 0; mt < 2; mt++)
#pragma unroll
        for (int nt = 0; nt < 8; nt++)
#pragma unroll
            for (int i = 0; i < 4; i++) c[mt][nt][i] = 0.f;

    // prefetch chunk 0 into stage 0
    issue_tiles(neigh, mlp_w, rowBase, 0, nBase, sm, sm + 128 * LDA, tid);
    CP_COMMIT();

    for (int kt = 0; kt < DIN / 32; kt++) {
        CP_WAIT0();
        __syncthreads();
        if (kt + 1 < DIN / 32) {
            float* st = sm + ((kt + 1) & 1) * STAGE_WORDS;
            issue_tiles(neigh, mlp_w, rowBase, kt + 1, nBase, st, st + 128 * LDA, tid);
            CP_COMMIT();
        }
        float* cu = sm + (kt & 1) * STAGE_WORDS;
        compute_chunk(cu, cu + 128 * LDA, c, warpM, warpN, g, tig);
    }

    // Epilogue: max over the warp's 32 rows (one neighbor group), + bias, relu.
    int group = blockIdx.y * 4 + warpM;
#pragma unroll
    for (int nt = 0; nt < 8; nt++) {
        float m0 = fmaxf(fmaxf(c[0][nt][0], c[0][nt][2]), fmaxf(c[1][nt][0], c[1][nt][2]));
        float m1 = fmaxf(fmaxf(c[0][nt][1], c[0][nt][3]), fmaxf(c[1][nt][1], c[1][nt][3]));
#pragma unroll
        for (int off = 4; off < 32; off <<= 1) {
            m0 = fmaxf(m0, __shfl_xor_sync(0xffffffffu, m0, off));
            m1 = fmaxf(m1, __shfl_xor_sync(0xffffffffu, m1, off));
        }
        if (g == 0) {
            int col = nBase + warpN * 64 + nt * 8 + 2 * tig;
            float b0 = mlp_b[col], b1 = mlp_b[col + 1];
            g_pooled[group * DHID + col]     = fmaxf(m0 + b0, 0.f);
            g_pooled[group * DHID + col + 1] = fmaxf(m1 + b1, 0.f);
        }
    }
}

// Kernel 2: out = relu(pooled @ neigh_w + self_vecs @ self_w) — fused 32-chunk pipeline
__global__ void __launch_bounds__(256, 2)
k_out(const float* __restrict__ selfv,
      const float* __restrict__ neigh_w,
      const float* __restrict__ self_w,
      float* __restrict__ out) {
    extern __shared__ float sm[];

    int tid  = threadIdx.x;
    int warp = tid >> 5, lane = tid & 31;
    int g = lane >> 2, tig = lane & 3;
    int warpM = warp & 3, warpN = warp >> 2;

    int rowBase = blockIdx.y * 128;
    int nBase   = blockIdx.x * 128;

    float c[2][8][4];
#pragma unroll
    for (int mt = 0; mt < 2; mt++)
#pragma unroll
        for (int nt = 0; nt < 8; nt++)
#pragma unroll
            for (int i = 0; i < 4; i++) c[mt][nt][i] = 0.f;

    const int NCHUNK = 2 * (DHID / 32);   // 32 virtual chunks: phase0=pooled@neigh_w, phase1=self@self_w

    // prefetch chunk 0
    issue_tiles(g_pooled, neigh_w, rowBase, 0, nBase, sm, sm + 128 * LDA, tid);
    CP_COMMIT();

    for (int u = 0; u < NCHUNK; u++) {
        CP_WAIT0();
        __syncthreads();
        if (u + 1 < NCHUNK) {
            int un = u + 1;
            const float* A = (un >= 16) ? selfv  : g_pooled;
            const float* W = (un >= 16) ? self_w : neigh_w;
            float* st = sm + ((un) & 1) * STAGE_WORDS;
            issue_tiles(A, W, rowBase, un & 15, nBase, st, st + 128 * LDA, tid);
            CP_COMMIT();
        }
        float* cu = sm + (u & 1) * STAGE_WORDS;
        compute_chunk(cu, cu + 128 * LDA, c, warpM, warpN, g, tig);
    }

#pragma unroll
    for (int mt = 0; mt < 2; mt++) {
#pragma unroll
        for (int nt = 0; nt < 8; nt++) {
            int row = rowBase + warpM * 32 + mt * 16 + g;
            int col = nBase + warpN * 64 + nt * 8 + 2 * tig;
            float2 v0 = make_float2(fmaxf(c[mt][nt][0], 0.f), fmaxf(c[mt][nt][1], 0.f));
            float2 v1 = make_float2(fmaxf(c[mt][nt][2], 0.f), fmaxf(c[mt][nt][3], 0.f));
            *reinterpret_cast<float2*>(out + row * DOUT + col)       = v0;
            *reinterpret_cast<float2*>(out + (row + 8) * DOUT + col) = v1;
        }
    }
}

extern "C" void kernel_launch(void* const* d_in, const int* in_sizes, int n_in,
                              void* d_out, int out_size) {
    const float* selfv   = (const float*)d_in[0];
    const float* neigh   = (const float*)d_in[1];
    const float* mlp_w   = (const float*)d_in[2];
    const float* mlp_b   = (const float*)d_in[3];
    const float* neigh_w = (const float*)d_in[4];
    const float* self_w  = (const float*)d_in[5];
    float* out = (float*)d_out;

    cudaFuncSetAttribute(k_mlp_maxpool, cudaFuncAttributeMaxDynamicSharedMemorySize, SMEM_BYTES);
    cudaFuncSetAttribute(k_out,         cudaFuncAttributeMaxDynamicSharedMemorySize, SMEM_BYTES);

    dim3 grid1(DHID / 128, (BATCH * NNEI) / 128);  // (4, 2048)
    k_mlp_maxpool<<<grid1, 256, SMEM_BYTES>>>(neigh, mlp_w, mlp_b);

    dim3 grid2(DOUT / 128, BATCH / 128);           // (4, 64)
    k_out<<<grid2, 256, SMEM_BYTES>>>(selfv, neigh_w, self_w, out);
}

// round 5
// speedup vs baseline: 1.4239x; 1.4239x over previous
#include <cuda_runtime.h>
#include <cstdint>

#define BATCH 8192
#define NNEI  32
#define DIN   512
#define DHID  512
#define DOUT  512

// ---------------- device scratch (no allocs allowed) ----------------
__device__ __align__(1024) float g_pooled[BATCH * DHID];   // 16 MB
__device__ __align__(1024) float g_wT[3 * 512 * 512];      // tf32-rounded, K-major [N,K]: mlp, neigh, self

// ---------------- helpers ----------------
__device__ __forceinline__ uint32_t f2tf(float x) {
    uint32_t r;
    asm("cvt.rna.tf32.f32 %0, %1;" : "=r"(r) : "f"(x));
    return r;
}
__device__ __forceinline__ uint32_t f2tf_bits(uint32_t x) {
    uint32_t r;
    asm("cvt.rna.tf32.f32 %0, %1;" : "=r"(r) : "r"(x));
    return r;
}

__device__ __forceinline__ uint32_t smem_u32(const void* p) {
    uint32_t a;
    asm("{ .reg .u64 t; cvta.to.shared.u64 t, %1; cvt.u32.u64 %0, t; }" : "=r"(a) : "l"(p));
    return a;
}

__device__ __forceinline__ uint32_t swz128(uint32_t b) { return b ^ ((b >> 3) & 0x70); }

__device__ __forceinline__ void cp_async16(uint32_t sdst, const float* gsrc) {
    asm volatile("cp.async.cg.shared.global [%0], [%1], 16;\n" :: "r"(sdst), "l"(gsrc));
}
#define CP_COMMIT() asm volatile("cp.async.commit_group;\n" ::: "memory")
#define CP_WAIT1()  asm volatile("cp.async.wait_group 1;\n" ::: "memory")

#define LDSM_X4(r0, r1, r2, r3, addr) \
    asm volatile("ldmatrix.sync.aligned.m8n8.x4.shared.b16 {%0,%1,%2,%3}, [%4];" \
        : "=r"(r0), "=r"(r1), "=r"(r2), "=r"(r3) : "r"(addr))

__device__ __forceinline__ void mma8(float* c,
                                     uint32_t a0, uint32_t a1, uint32_t a2, uint32_t a3,
                                     uint32_t b0, uint32_t b1) {
    asm volatile(
        "mma.sync.aligned.m16n8k8.row.col.f32.tf32.tf32.f32 "
        "{%0,%1,%2,%3},{%4,%5,%6,%7},{%8,%9},{%0,%1,%2,%3};\n"
        : "+f"(c[0]), "+f"(c[1]), "+f"(c[2]), "+f"(c[3])
        : "r"(a0), "r"(a1), "r"(a2), "r"(a3), "r"(b0), "r"(b1));
}

// ---------------- SMEM layout: 3 stages x 32KB (A 128x32 @ +0, B 128x32 @ +16384) ----
#define STAGE_BYTES 32768
#define B_OFF       16384
#define SMEM_TOTAL  (3 * STAGE_BYTES)

// issue one K-chunk (32 wide) of A[128 rows] and Bt[128 n-rows] into a stage, SW128 swizzled
__device__ __forceinline__ void issue_chunk(const float* __restrict__ A,
                                            const float* __restrict__ Bt,
                                            int rowBase, int nBase, int kt,
                                            uint32_t stage, int tid) {
#pragma unroll
    for (int j = 0; j < 4; j++) {
        int pos = tid + j * 256;           // 128 rows x 8 (16B units)
        int r = pos >> 3, c = pos & 7;
        cp_async16(stage + swz128(r * 128 + c * 16),
                   A + (rowBase + r) * 512 + kt * 32 + c * 4);
    }
#pragma unroll
    for (int j = 0; j < 4; j++) {
        int pos = tid + j * 256;
        int r = pos >> 3, c = pos & 7;
        cp_async16(stage + B_OFF + swz128(r * 128 + c * 16),
                   Bt + (nBase + r) * 512 + kt * 32 + c * 4);
    }
}

// One K-chunk of MMAs for this warp's 32x64 tile via ldmatrix fragments.
__device__ __forceinline__ void compute_chunk(uint32_t aBase, uint32_t bBase,
                                              float c[2][8][4],
                                              int warpM, int warpN, int lane) {
    uint32_t xorv = (uint32_t)(lane & 7) << 4;
    int rA = warpM * 32 + (lane & 7) + ((lane >> 3) & 1) * 8;
    uint32_t aRow = aBase + rA * 128;
    uint32_t cA = (uint32_t)(lane >> 4) * 16;
    int nB = warpN * 64 + ((lane >> 4) & 1) * 8 + (lane & 7);
    uint32_t bRow = bBase + nB * 128;
    uint32_t cB = (uint32_t)((lane >> 3) & 1) * 16;

#pragma unroll
    for (int k8 = 0; k8 < 4; k8++) {
        uint32_t offA = (k8 * 32 + cA) ^ xorv;
        uint32_t offB = (k8 * 32 + cB) ^ xorv;
        uint32_t a[2][4];
        LDSM_X4(a[0][0], a[0][1], a[0][2], a[0][3], aRow + offA);
        LDSM_X4(a[1][0], a[1][1], a[1][2], a[1][3], aRow + 2048 + offA);
        uint32_t b[8][2];
#pragma unroll
        for (int np = 0; np < 4; np++) {
            uint32_t b0, b1, b2, b3;
            LDSM_X4(b0, b1, b2, b3, bRow + np * 2048 + offB);
            b[2 * np][0] = b0; b[2 * np][1] = b1;
            b[2 * np + 1][0] = b2; b[2 * np + 1][1] = b3;
        }
#pragma unroll
        for (int mt = 0; mt < 2; mt++)
#pragma unroll
            for (int i = 0; i < 4; i++) a[mt][i] = f2tf_bits(a[mt][i]);
#pragma unroll
        for (int mt = 0; mt < 2; mt++)
#pragma unroll
            for (int nt = 0; nt < 8; nt++)
                mma8(c[mt][nt], a[mt][0], a[mt][1], a[mt][2], a[mt][3],
                     b[nt][0], b[nt][1]);
    }
}

// Shared 3-stage pipelined mainloop. sel(u) -> (A, Bt, kt).
template <int NCHUNK, typename SEL>
__device__ __forceinline__ void gemm_mainloop(SEL sel, int rowBase, int nBase,
                                              uint32_t sbase, float c[2][8][4],
                                              int tid, int warpM, int warpN, int lane) {
    {
        const float *A, *B; int kt;
        sel(0, A, B, kt); issue_chunk(A, B, rowBase, nBase, kt, sbase, tid); CP_COMMIT();
        sel(1, A, B, kt); issue_chunk(A, B, rowBase, nBase, kt, sbase + STAGE_BYTES, tid); CP_COMMIT();
    }
    uint32_t stage_off = 0;
    for (int u = 0; u < NCHUNK; u++) {
        CP_WAIT1();
        __syncthreads();
        if (u + 2 < NCHUNK) {
            const float *A, *B; int kt;
            sel(u + 2, A, B, kt);
            uint32_t so = stage_off + 2 * STAGE_BYTES;
            if (so >= 3 * STAGE_BYTES) so -= 3 * STAGE_BYTES;
            issue_chunk(A, B, rowBase, nBase, kt, sbase + so, tid);
        }
        CP_COMMIT();
        compute_chunk(sbase + stage_off, sbase + stage_off + B_OFF, c, warpM, warpN, lane);
        stage_off += STAGE_BYTES;
        if (stage_off == 3 * STAGE_BYTES) stage_off = 0;
    }
}

// ---------------- Kernel 1: h = neigh @ mlp_w; pooled = relu(max32(h) + b) ----------------
__global__ void __launch_bounds__(256, 2)
k_mlp_maxpool(const float* __restrict__ neigh, const float* __restrict__ mlp_b) {
    extern __shared__ char sm[];
    int tid = threadIdx.x, warp = tid >> 5, lane = tid & 31;
    int g = lane >> 2, tig = lane & 3;
    int warpM = warp & 3, warpN = warp >> 2;     // 4 x 2
    int rowBase = blockIdx.y * 128;
    int nBase   = blockIdx.x * 128;
    uint32_t sbase = smem_u32(sm);

    float c[2][8][4];
#pragma unroll
    for (int mt = 0; mt < 2; mt++)
#pragma unroll
        for (int nt = 0; nt < 8; nt++)
#pragma unroll
            for (int i = 0; i < 4; i++) c[mt][nt][i] = 0.f;

    const float* wT = g_wT;
    auto sel = [&](int u, const float*& A, const float*& B, int& kt) {
        A = neigh; B = wT; kt = u;
    };
    gemm_mainloop<16>(sel, rowBase, nBase, sbase, c, tid, warpM, warpN, lane);

    // warp's 32 rows = one pool group
    int group = blockIdx.y * 4 + warpM;
#pragma unroll
    for (int nt = 0; nt < 8; nt++) {
        float m0 = fmaxf(fmaxf(c[0][nt][0], c[0][nt][2]), fmaxf(c[1][nt][0], c[1][nt][2]));
        float m1 = fmaxf(fmaxf(c[0][nt][1], c[0][nt][3]), fmaxf(c[1][nt][1], c[1][nt][3]));
#pragma unroll
        for (int off = 4; off < 32; off <<= 1) {
            m0 = fmaxf(m0, __shfl_xor_sync(0xffffffffu, m0, off));
            m1 = fmaxf(m1, __shfl_xor_sync(0xffffffffu, m1, off));
        }
        if (g == 0) {
            int col = nBase + warpN * 64 + nt * 8 + 2 * tig;
            float b0 = mlp_b[col], b1 = mlp_b[col + 1];
            g_pooled[group * DHID + col]     = fmaxf(m0 + b0, 0.f);
            g_pooled[group * DHID + col + 1] = fmaxf(m1 + b1, 0.f);
        }
    }
}

// ---------------- Kernel 2: out = relu(pooled @ neigh_w + self @ self_w) ----------------
__global__ void __launch_bounds__(256, 2)
k_out(const float* __restrict__ selfv, float* __restrict__ out) {
    extern __shared__ char sm[];
    int tid = threadIdx.x, warp = tid >> 5, lane = tid & 31;
    int g = lane >> 2, tig = lane & 3;
    int warpM = warp & 3, warpN = warp >> 2;
    int rowBase = blockIdx.y * 128;
    int nBase   = blockIdx.x * 128;
    uint32_t sbase = smem_u32(sm);

    float c[2][8][4];
#pragma unroll
    for (int mt = 0; mt < 2; mt++)
#pragma unroll
        for (int nt = 0; nt < 8; nt++)
#pragma unroll
            for (int i = 0; i < 4; i++) c[mt][nt][i] = 0.f;

    const float* neigh_wT = g_wT + 512 * 512;
    const float* self_wT  = g_wT + 2 * 512 * 512;
    auto sel = [&](int u, const float*& A, const float*& B, int& kt) {
        if (u < 16) { A = g_pooled; B = neigh_wT; } else { A = selfv; B = self_wT; }
        kt = u & 15;
    };
    gemm_mainloop<32>(sel, rowBase, nBase, sbase, c, tid, warpM, warpN, lane);

#pragma unroll
    for (int mt = 0; mt < 2; mt++) {
#pragma unroll
        for (int nt = 0; nt < 8; nt++) {
            int row = rowBase + warpM * 32 + mt * 16 + g;
            int col = nBase + warpN * 64 + nt * 8 + 2 * tig;
            float2 v0 = make_float2(fmaxf(c[mt][nt][0], 0.f), fmaxf(c[mt][nt][1], 0.f));
            float2 v1 = make_float2(fmaxf(c[mt][nt][2], 0.f), fmaxf(c[mt][nt][3], 0.f));
            *reinterpret_cast<float2*>(out + row * DOUT + col)       = v0;
            *reinterpret_cast<float2*>(out + (row + 8) * DOUT + col) = v1;
        }
    }
}

// ---------------- Weight transpose + tf32 pre-round: [K,N] -> K-major [N,K] ----------------
__global__ void __launch_bounds__(256)
k_transpose(const float* __restrict__ w0, const float* __restrict__ w1,
            const float* __restrict__ w2) {
    const float* src = (blockIdx.z == 0) ? w0 : (blockIdx.z == 1) ? w1 : w2;
    float* dst = g_wT + blockIdx.z * (512 * 512);
    __shared__ float t[32][33];
    int bx = blockIdx.x * 32, by = blockIdx.y * 32;
    int tx = threadIdx.x & 31, ty = threadIdx.x >> 5;
#pragma unroll
    for (int i = 0; i < 4; i++)
        t[ty + i * 8][tx] = src[(by + ty + i * 8) * 512 + bx + tx];
    __syncthreads();
#pragma unroll
    for (int i = 0; i < 4; i++)
        dst[(bx + ty + i * 8) * 512 + by + tx] = __uint_as_float(f2tf(t[tx][ty + i * 8]));
}

extern "C" void kernel_launch(void* const* d_in, const int* in_sizes, int n_in,
                              void* d_out, int out_size) {
    const float* selfv   = (const float*)d_in[0];
    const float* neigh   = (const float*)d_in[1];
    const float* mlp_w   = (const float*)d_in[2];
    const float* mlp_b   = (const float*)d_in[3];
    const float* neigh_w = (const float*)d_in[4];
    const float* self_w  = (const float*)d_in[5];
    float* out = (float*)d_out;

    cudaFuncSetAttribute(k_mlp_maxpool, cudaFuncAttributeMaxDynamicSharedMemorySize, SMEM_TOTAL);
    cudaFuncSetAttribute(k_out,         cudaFuncAttributeMaxDynamicSharedMemorySize, SMEM_TOTAL);

    k_transpose<<<dim3(16, 16, 3), 256>>>(mlp_w, neigh_w, self_w);

    dim3 grid1(DHID / 128, (BATCH * NNEI) / 128);   // (4, 2048)
    k_mlp_maxpool<<<grid1, 256, SMEM_TOTAL>>>(neigh, mlp_b);

    dim3 grid2(DOUT / 128, BATCH / 128);            // (4, 64)
    k_out<<<grid2, 256, SMEM_TOTAL>>>(selfv, out);
}

// round 6
// speedup vs baseline: 1.4921x; 1.0480x over previous
#include <cuda_runtime.h>
#include <cstdint>

#define BATCH 8192
#define NNEI  32
#define DIN   512
#define DHID  512
#define DOUT  512

// ---------------- device scratch (no allocs allowed) ----------------
__device__ __align__(1024) float g_pooled[BATCH * DHID];   // 16 MB, stored pre-rounded to tf32
__device__ __align__(1024) float g_wT[3 * 512 * 512];      // tf32-rounded, K-major [N,K]: mlp, neigh, self

// Compensation for HW truncation (round-toward-zero) of raw fp32 A operands:
// E[rel shrink] = E[u * 2^-10 / m] ~= 3.45e-4 -> pre-scale the paired weights.
#define TRUNC_COMP 1.000345f

// ---------------- helpers ----------------
__device__ __forceinline__ uint32_t f2tf(float x) {
    uint32_t r;
    asm("cvt.rna.tf32.f32 %0, %1;" : "=r"(r) : "f"(x));
    return r;
}

__device__ __forceinline__ uint32_t smem_u32(const void* p) {
    uint32_t a;
    asm("{ .reg .u64 t; cvta.to.shared.u64 t, %1; cvt.u32.u64 %0, t; }" : "=r"(a) : "l"(p));
    return a;
}

__device__ __forceinline__ uint32_t swz128(uint32_t b) { return b ^ ((b >> 3) & 0x70); }

__device__ __forceinline__ void cp_async16(uint32_t sdst, const float* gsrc) {
    asm volatile("cp.async.cg.shared.global [%0], [%1], 16;\n" :: "r"(sdst), "l"(gsrc));
}
#define CP_COMMIT() asm volatile("cp.async.commit_group;\n" ::: "memory")
#define CP_WAIT1()  asm volatile("cp.async.wait_group 1;\n" ::: "memory")

#define LDSM_X4(r0, r1, r2, r3, addr) \
    asm volatile("ldmatrix.sync.aligned.m8n8.x4.shared.b16 {%0,%1,%2,%3}, [%4];" \
        : "=r"(r0), "=r"(r1), "=r"(r2), "=r"(r3) : "r"(addr))

__device__ __forceinline__ void mma8(float* c,
                                     uint32_t a0, uint32_t a1, uint32_t a2, uint32_t a3,
                                     uint32_t b0, uint32_t b1) {
    asm volatile(
        "mma.sync.aligned.m16n8k8.row.col.f32.tf32.tf32.f32 "
        "{%0,%1,%2,%3},{%4,%5,%6,%7},{%8,%9},{%0,%1,%2,%3};\n"
        : "+f"(c[0]), "+f"(c[1]), "+f"(c[2]), "+f"(c[3])
        : "r"(a0), "r"(a1), "r"(a2), "r"(a3), "r"(b0), "r"(b1));
}

// ---------------- SMEM layout: 3 stages x 32KB (A 128x32 @ +0, B 128x32 @ +16384) ----
#define STAGE_BYTES 32768
#define B_OFF       16384
#define SMEM_TOTAL  (3 * STAGE_BYTES)

// issue one K-chunk (32 wide) of A[128 rows] and Bt[128 n-rows] into a stage, SW128 swizzled
__device__ __forceinline__ void issue_chunk(const float* __restrict__ A,
                                            const float* __restrict__ Bt,
                                            int rowBase, int nBase, int kt,
                                            uint32_t stage, int tid) {
#pragma unroll
    for (int j = 0; j < 4; j++) {
        int pos = tid + j * 256;           // 128 rows x 8 (16B units)
        int r = pos >> 3, c = pos & 7;
        cp_async16(stage + swz128(r * 128 + c * 16),
                   A + (rowBase + r) * 512 + kt * 32 + c * 4);
    }
#pragma unroll
    for (int j = 0; j < 4; j++) {
        int pos = tid + j * 256;
        int r = pos >> 3, c = pos & 7;
        cp_async16(stage + B_OFF + swz128(r * 128 + c * 16),
                   Bt + (nBase + r) * 512 + kt * 32 + c * 4);
    }
}

// One K-chunk of MMAs for this warp's 32x64 tile via ldmatrix fragments.
// A fragments are fed RAW (HW truncation; compensated via weight pre-scaling).
__device__ __forceinline__ void compute_chunk(uint32_t aBase, uint32_t bBase,
                                              float c[2][8][4],
                                              int warpM, int warpN, int lane) {
    uint32_t xorv = (uint32_t)(lane & 7) << 4;
    int rA = warpM * 32 + (lane & 7) + ((lane >> 3) & 1) * 8;
    uint32_t aRow = aBase + rA * 128;
    uint32_t cA = (uint32_t)(lane >> 4) * 16;
    int nB = warpN * 64 + ((lane >> 4) & 1) * 8 + (lane & 7);
    uint32_t bRow = bBase + nB * 128;
    uint32_t cB = (uint32_t)((lane >> 3) & 1) * 16;

#pragma unroll
    for (int k8 = 0; k8 < 4; k8++) {
        uint32_t offA = (k8 * 32 + cA) ^ xorv;
        uint32_t offB = (k8 * 32 + cB) ^ xorv;
        uint32_t a[2][4];
        LDSM_X4(a[0][0], a[0][1], a[0][2], a[0][3], aRow + offA);
        LDSM_X4(a[1][0], a[1][1], a[1][2], a[1][3], aRow + 2048 + offA);
        uint32_t b[8][2];
#pragma unroll
        for (int np = 0; np < 4; np++) {
            uint32_t b0, b1, b2, b3;
            LDSM_X4(b0, b1, b2, b3, bRow + np * 2048 + offB);
            b[2 * np][0] = b0; b[2 * np][1] = b1;
            b[2 * np + 1][0] = b2; b[2 * np + 1][1] = b3;
        }
#pragma unroll
        for (int mt = 0; mt < 2; mt++)
#pragma unroll
            for (int nt = 0; nt < 8; nt++)
                mma8(c[mt][nt], a[mt][0], a[mt][1], a[mt][2], a[mt][3],
                     b[nt][0], b[nt][1]);
    }
}

// Shared 3-stage pipelined mainloop. sel(u) -> (A, Bt, kt).
template <int NCHUNK, typename SEL>
__device__ __forceinline__ void gemm_mainloop(SEL sel, int rowBase, int nBase,
                                              uint32_t sbase, float c[2][8][4],
                                              int tid, int warpM, int warpN, int lane) {
    {
        const float *A, *B; int kt;
        sel(0, A, B, kt); issue_chunk(A, B, rowBase, nBase, kt, sbase, tid); CP_COMMIT();
        sel(1, A, B, kt); issue_chunk(A, B, rowBase, nBase, kt, sbase + STAGE_BYTES, tid); CP_COMMIT();
    }
    uint32_t stage_off = 0;
    for (int u = 0; u < NCHUNK; u++) {
        CP_WAIT1();
        __syncthreads();
        if (u + 2 < NCHUNK) {
            const float *A, *B; int kt;
            sel(u + 2, A, B, kt);
            uint32_t so = stage_off + 2 * STAGE_BYTES;
            if (so >= 3 * STAGE_BYTES) so -= 3 * STAGE_BYTES;
            issue_chunk(A, B, rowBase, nBase, kt, sbase + so, tid);
        }
        CP_COMMIT();
        compute_chunk(sbase + stage_off, sbase + stage_off + B_OFF, c, warpM, warpN, lane);
        stage_off += STAGE_BYTES;
        if (stage_off == 3 * STAGE_BYTES) stage_off = 0;
    }
}

// ---------------- Kernel 1: h = neigh @ mlp_w; pooled = relu(max32(h) + b) ----------------
__global__ void __launch_bounds__(256, 2)
k_mlp_maxpool(const float* __restrict__ neigh, const float* __restrict__ mlp_b) {
    extern __shared__ char sm[];
    int tid = threadIdx.x, warp = tid >> 5, lane = tid & 31;
    int g = lane >> 2, tig = lane & 3;
    int warpM = warp & 3, warpN = warp >> 2;     // 4 x 2
    int rowBase = blockIdx.y * 128;
    int nBase   = blockIdx.x * 128;
    uint32_t sbase = smem_u32(sm);

    float c[2][8][4];
#pragma unroll
    for (int mt = 0; mt < 2; mt++)
#pragma unroll
        for (int nt = 0; nt < 8; nt++)
#pragma unroll
            for (int i = 0; i < 4; i++) c[mt][nt][i] = 0.f;

    const float* wT = g_wT;
    auto sel = [&](int u, const float*& A, const float*& B, int& kt) {
        A = neigh; B = wT; kt = u;
    };
    gemm_mainloop<16>(sel, rowBase, nBase, sbase, c, tid, warpM, warpN, lane);

    // warp's 32 rows = one pool group; store pooled pre-rounded to tf32 so k2's
    // A-side truncation is a no-op (exact).
    int group = blockIdx.y * 4 + warpM;
#pragma unroll
    for (int nt = 0; nt < 8; nt++) {
        float m0 = fmaxf(fmaxf(c[0][nt][0], c[0][nt][2]), fmaxf(c[1][nt][0], c[1][nt][2]));
        float m1 = fmaxf(fmaxf(c[0][nt][1], c[0][nt][3]), fmaxf(c[1][nt][1], c[1][nt][3]));
#pragma unroll
        for (int off = 4; off < 32; off <<= 1) {
            m0 = fmaxf(m0, __shfl_xor_sync(0xffffffffu, m0, off));
            m1 = fmaxf(m1, __shfl_xor_sync(0xffffffffu, m1, off));
        }
        if (g == 0) {
            int col = nBase + warpN * 64 + nt * 8 + 2 * tig;
            float b0 = mlp_b[col], b1 = mlp_b[col + 1];
            float p0 = fmaxf(m0 + b0, 0.f);
            float p1 = fmaxf(m1 + b1, 0.f);
            g_pooled[group * DHID + col]     = __uint_as_float(f2tf(p0));
            g_pooled[group * DHID + col + 1] = __uint_as_float(f2tf(p1));
        }
    }
}

// ---------------- Kernel 2: out = relu(pooled @ neigh_w + self @ self_w) ----------------
__global__ void __launch_bounds__(256, 2)
k_out(const float* __restrict__ selfv, float* __restrict__ out) {
    extern __shared__ char sm[];
    int tid = threadIdx.x, warp = tid >> 5, lane = tid & 31;
    int g = lane >> 2, tig = lane & 3;
    int warpM = warp & 3, warpN = warp >> 2;
    int rowBase = blockIdx.y * 128;
    int nBase   = blockIdx.x * 128;
    uint32_t sbase = smem_u32(sm);

    float c[2][8][4];
#pragma unroll
    for (int mt = 0; mt < 2; mt++)
#pragma unroll
        for (int nt = 0; nt < 8; nt++)
#pragma unroll
            for (int i = 0; i < 4; i++) c[mt][nt][i] = 0.f;

    const float* neigh_wT = g_wT + 512 * 512;
    const float* self_wT  = g_wT + 2 * 512 * 512;
    auto sel = [&](int u, const float*& A, const float*& B, int& kt) {
        if (u < 16) { A = g_pooled; B = neigh_wT; } else { A = selfv; B = self_wT; }
        kt = u & 15;
    };
    gemm_mainloop<32>(sel, rowBase, nBase, sbase, c, tid, warpM, warpN, lane);

#pragma unroll
    for (int mt = 0; mt < 2; mt++) {
#pragma unroll
        for (int nt = 0; nt < 8; nt++) {
            int row = rowBase + warpM * 32 + mt * 16 + g;
            int col = nBase + warpN * 64 + nt * 8 + 2 * tig;
            float2 v0 = make_float2(fmaxf(c[mt][nt][0], 0.f), fmaxf(c[mt][nt][1], 0.f));
            float2 v1 = make_float2(fmaxf(c[mt][nt][2], 0.f), fmaxf(c[mt][nt][3], 0.f));
            *reinterpret_cast<float2*>(out + row * DOUT + col)       = v0;
            *reinterpret_cast<float2*>(out + (row + 8) * DOUT + col) = v1;
        }
    }
}

// ---------------- Weight transpose + compensate + tf32 pre-round: [K,N] -> K-major [N,K] ----
__global__ void __launch_bounds__(256)
k_transpose(const float* __restrict__ w0, const float* __restrict__ w1,
            const float* __restrict__ w2) {
    const float* src = (blockIdx.z == 0) ? w0 : (blockIdx.z == 1) ? w1 : w2;
    // mlp_w (z=0) and self_w (z=2) pair with truncated raw-fp32 A operands -> compensate.
    // neigh_w (z=1) pairs with pre-rounded tf32 pooled -> exact, no compensation.
    float scale = (blockIdx.z == 1) ? 1.0f : TRUNC_COMP;
    float* dst = g_wT + blockIdx.z * (512 * 512);
    __shared__ float t[32][33];
    int bx = blockIdx.x * 32, by = blockIdx.y * 32;
    int tx = threadIdx.x & 31, ty = threadIdx.x >> 5;
#pragma unroll
    for (int i = 0; i < 4; i++)
        t[ty + i * 8][tx] = src[(by + ty + i * 8) * 512 + bx + tx];
    __syncthreads();
#pragma unroll
    for (int i = 0; i < 4; i++)
        dst[(bx + ty + i * 8) * 512 + by + tx] = __uint_as_float(f2tf(t[tx][ty + i * 8] * scale));
}

extern "C" void kernel_launch(void* const* d_in, const int* in_sizes, int n_in,
                              void* d_out, int out_size) {
    const float* selfv   = (const float*)d_in[0];
    const float* neigh   = (const float*)d_in[1];
    const float* mlp_w   = (const float*)d_in[2];
    const float* mlp_b   = (const float*)d_in[3];
    const float* neigh_w = (const float*)d_in[4];
    const float* self_w  = (const float*)d_in[5];
    float* out = (float*)d_out;

    cudaFuncSetAttribute(k_mlp_maxpool, cudaFuncAttributeMaxDynamicSharedMemorySize, SMEM_TOTAL);
    cudaFuncSetAttribute(k_out,         cudaFuncAttributeMaxDynamicSharedMemorySize, SMEM_TOTAL);

    k_transpose<<<dim3(16, 16, 3), 256>>>(mlp_w, neigh_w, self_w);

    dim3 grid1(DHID / 128, (BATCH * NNEI) / 128);   // (4, 2048)
    k_mlp_maxpool<<<grid1, 256, SMEM_TOTAL>>>(neigh, mlp_b);

    dim3 grid2(DOUT / 128, BATCH / 128);            // (4, 64)
    k_out<<<grid2, 256, SMEM_TOTAL>>>(selfv, out);
}